// round 11
// baseline (speedup 1.0000x reference)
#include <cuda_runtime.h>
#include <cuda_bf16.h>

#define N_CORES   64
#define N_QUBITS  1024
#define QEMB      256
#define N_EDGES   448
#define BATCH     512

// Scratch: ping-pong activation buffers, max width 512.
__device__ float g_buf0[BATCH * N_CORES * 512];
__device__ float g_buf1[BATCH * N_CORES * 512];
__device__ float g_A[N_CORES * N_CORES];

// ---------------------------------------------------------------------------
// Kernel 1: build dense normalized adjacency A[col][row] (with self loops)
// ---------------------------------------------------------------------------
__global__ void prep_A_kernel(const int* __restrict__ eidx,
                              const float* __restrict__ ew,
                              float* __restrict__ A_out)
{
    __shared__ float sdeg[N_CORES];
    __shared__ float sdinv[N_CORES];
    __shared__ float sA[N_CORES * N_CORES];
    const int t = threadIdx.x;  // 256 threads

    if (t < N_CORES) sdeg[t] = 1.0f;  // self-loop weight
    for (int i = t; i < N_CORES * N_CORES; i += 256) sA[i] = 0.0f;
    __syncthreads();

    // deg = segment_sum(w, col) + 1 (self loops)
    for (int e = t; e < N_EDGES; e += 256) {
        int c = eidx[N_EDGES + e];
        atomicAdd(&sdeg[c], ew[e]);
    }
    __syncthreads();

    if (t < N_CORES) sdinv[t] = 1.0f / sqrtf(sdeg[t]);  // deg >= 1 always
    __syncthreads();

    for (int e = t; e < N_EDGES; e += 256) {
        int r = eidx[e];
        int c = eidx[N_EDGES + e];
        atomicAdd(&sA[c * N_CORES + r], sdinv[r] * ew[e] * sdinv[c]);
    }
    if (t < N_CORES) {
        atomicAdd(&sA[t * N_CORES + t], sdinv[t] * sdinv[t]);  // self loop
    }
    __syncthreads();

    for (int i = t; i < N_CORES * N_CORES; i += 256) A_out[i] = sA[i];
}

// ---------------------------------------------------------------------------
// Kernel 2: pooling. grid = (BATCH, 2); block = 128 threads (one per dim in
// this half). Each thread owns dim d = half*128 + t for all 64 cores -> no
// atomics needed (sequential max updates per thread).
// ---------------------------------------------------------------------------
__global__ void pool_kernel(const int* __restrict__ core_allocs,
                            const float* __restrict__ qubit_embs,
                            const float* __restrict__ dummy_emb,
                            float* __restrict__ x0)
{
    __shared__ int   s_alloc[N_QUBITS];
    __shared__ float smax[N_CORES * 128];

    const int b    = blockIdx.x;
    const int half = blockIdx.y;          // 0 or 1
    const int t    = threadIdx.x;         // 0..127
    const int d    = half * 128 + t;      // embedding dim

    // stage this batch's alloc row
    const int* arow = core_allocs + b * N_QUBITS;
    for (int q = t; q < N_QUBITS; q += 128) s_alloc[q] = arow[q];

    // init to dummy (covers empty cores AND the always-included dummy)
    const float dv = dummy_emb[d];
    #pragma unroll
    for (int c = 0; c < N_CORES; c++) smax[c * 128 + t] = dv;
    __syncthreads();

    // scatter-max over all qubits (thread t owns column t -> race-free)
    #pragma unroll 4
    for (int q = 0; q < N_QUBITS; q++) {
        int c = s_alloc[q];
        float v = __ldg(&qubit_embs[q * QEMB + d]);
        float* p = &smax[c * 128 + t];
        *p = fmaxf(*p, v);
    }
    __syncthreads();

    // write out x0[b][c][d]
    float* xb = x0 + (size_t)b * N_CORES * QEMB;
    #pragma unroll
    for (int c = 0; c < N_CORES; c++) {
        xb[c * QEMB + d] = smax[c * 128 + t];
    }
}

// ---------------------------------------------------------------------------
// Kernel 3: fused GCN layer  out = relu(A @ (x @ W) + b)
// grid = (DOUT/64, BATCH), block = 256 threads.
// Phase 1: H = x_b @ W[:, n0:n0+64]   (64 x DIN) @ (DIN x 64) register-tiled
// Phase 2: out = relu(A @ H + bias)
// ---------------------------------------------------------------------------
template <int DIN, int DOUT>
__global__ __launch_bounds__(256, 2)
void gcn_layer_kernel(const float* __restrict__ x,
                      const float* __restrict__ W,
                      const float* __restrict__ bias,
                      const float* __restrict__ A,
                      float* __restrict__ out)
{
    // Shared: sA padded [64][65]; sbuf aliased between
    //   phase1: sX [64][33] (2112) + sW [32][64] (2048)
    //   phase2: sH [64][64] (4096)
    __shared__ float sA[N_CORES * 65];
    __shared__ float sbuf[4352];
    float* sX = sbuf;            // stride 33
    float* sW = sbuf + 2112;     // stride 64
    float* sH = sbuf;            // stride 64

    const int b   = blockIdx.y;
    const int n0  = blockIdx.x * 64;
    const int tid = threadIdx.x;
    const int tx  = tid & 15;
    const int ty  = tid >> 4;
    const int tx4 = tx * 4;
    const int ty4 = ty * 4;

    // Load A into padded smem (conflict-free scalar reads later)
    for (int i = tid; i < N_CORES * N_CORES; i += 256)
        sA[(i >> 6) * 65 + (i & 63)] = A[i];

    const float* xb = x + (size_t)b * N_CORES * DIN;

    float acc[4][4];
    #pragma unroll
    for (int i = 0; i < 4; i++)
        #pragma unroll
        for (int j = 0; j < 4; j++) acc[i][j] = 0.0f;

    // ---- Phase 1: H = x_b @ W tile, K-chunks of 32 ----
    for (int k0 = 0; k0 < DIN; k0 += 32) {
        // load x chunk [64 x 32] -> sX (padded stride 33)
        #pragma unroll
        for (int i = 0; i < 2; i++) {
            int idx = tid + i * 256;           // 0..511 float4 slots
            int r   = idx >> 3;                // 8 float4 per row
            int kk4 = (idx & 7) * 4;
            float4 v = *(const float4*)(xb + r * DIN + k0 + kk4);
            float* dst = &sX[r * 33 + kk4];
            dst[0] = v.x; dst[1] = v.y; dst[2] = v.z; dst[3] = v.w;
        }
        // load W chunk [32 x 64] -> sW (stride 64, float4 both ways)
        #pragma unroll
        for (int i = 0; i < 2; i++) {
            int idx = tid + i * 256;           // 0..511 float4 slots
            int kk  = idx >> 4;                // 16 float4 per row
            int n4  = (idx & 15) * 4;
            float4 v = *(const float4*)(W + (size_t)(k0 + kk) * DOUT + n0 + n4);
            *(float4*)&sW[kk * 64 + n4] = v;
        }
        __syncthreads();

        #pragma unroll
        for (int kk = 0; kk < 32; kk++) {
            float a0 = sX[(ty4 + 0) * 33 + kk];
            float a1 = sX[(ty4 + 1) * 33 + kk];
            float a2 = sX[(ty4 + 2) * 33 + kk];
            float a3 = sX[(ty4 + 3) * 33 + kk];
            float4 bv = *(float4*)&sW[kk * 64 + tx4];
            acc[0][0] += a0 * bv.x; acc[0][1] += a0 * bv.y;
            acc[0][2] += a0 * bv.z; acc[0][3] += a0 * bv.w;
            acc[1][0] += a1 * bv.x; acc[1][1] += a1 * bv.y;
            acc[1][2] += a1 * bv.z; acc[1][3] += a1 * bv.w;
            acc[2][0] += a2 * bv.x; acc[2][1] += a2 * bv.y;
            acc[2][2] += a2 * bv.z; acc[2][3] += a2 * bv.w;
            acc[3][0] += a3 * bv.x; acc[3][1] += a3 * bv.y;
            acc[3][2] += a3 * bv.z; acc[3][3] += a3 * bv.w;
        }
        __syncthreads();
    }

    // ---- stage H into smem (aliases sX/sW; safe: all threads past sync) ----
    #pragma unroll
    for (int i = 0; i < 4; i++) {
        float4 v = make_float4(acc[i][0], acc[i][1], acc[i][2], acc[i][3]);
        *(float4*)&sH[(ty4 + i) * 64 + tx4] = v;
    }
    __syncthreads();

    // ---- Phase 2: out = relu(A @ H + bias) ----
    float o[4][4];
    #pragma unroll
    for (int i = 0; i < 4; i++)
        #pragma unroll
        for (int j = 0; j < 4; j++) o[i][j] = 0.0f;

    #pragma unroll
    for (int k = 0; k < N_CORES; k++) {
        float a0 = sA[(ty4 + 0) * 65 + k];
        float a1 = sA[(ty4 + 1) * 65 + k];
        float a2 = sA[(ty4 + 2) * 65 + k];
        float a3 = sA[(ty4 + 3) * 65 + k];
        float4 hv = *(float4*)&sH[k * 64 + tx4];
        o[0][0] += a0 * hv.x; o[0][1] += a0 * hv.y;
        o[0][2] += a0 * hv.z; o[0][3] += a0 * hv.w;
        o[1][0] += a1 * hv.x; o[1][1] += a1 * hv.y;
        o[1][2] += a1 * hv.z; o[1][3] += a1 * hv.w;
        o[2][0] += a2 * hv.x; o[2][1] += a2 * hv.y;
        o[2][2] += a2 * hv.z; o[2][3] += a2 * hv.w;
        o[3][0] += a3 * hv.x; o[3][1] += a3 * hv.y;
        o[3][2] += a3 * hv.z; o[3][3] += a3 * hv.w;
    }

    float4 bv = *(const float4*)(bias + n0 + tx4);
    float* ob = out + (size_t)b * N_CORES * DOUT;
    #pragma unroll
    for (int i = 0; i < 4; i++) {
        float4 r;
        r.x = fmaxf(o[i][0] + bv.x, 0.0f);
        r.y = fmaxf(o[i][1] + bv.y, 0.0f);
        r.z = fmaxf(o[i][2] + bv.z, 0.0f);
        r.w = fmaxf(o[i][3] + bv.w, 0.0f);
        *(float4*)(ob + (ty4 + i) * DOUT + n0 + tx4) = r;
    }
}

// ---------------------------------------------------------------------------
// Launch
// ---------------------------------------------------------------------------
extern "C" void kernel_launch(void* const* d_in, const int* in_sizes, int n_in,
                              void* d_out, int out_size)
{
    const int*   core_allocs = (const int*)d_in[0];    // [512,1024]
    const float* qubit_embs  = (const float*)d_in[1];  // [1024,256]
    const float* dummy_emb   = (const float*)d_in[2];  // [256]
    const int*   edge_index  = (const int*)d_in[3];    // [2,448]
    const float* edge_weight = (const float*)d_in[4];  // [448]
    const float* W1 = (const float*)d_in[5];           // [256,512]
    const float* b1 = (const float*)d_in[6];           // [512]
    const float* W2 = (const float*)d_in[7];           // [512,512]
    const float* b2 = (const float*)d_in[8];           // [512]
    const float* W3 = (const float*)d_in[9];           // [512,256]
    const float* b3 = (const float*)d_in[10];          // [256]
    float* out = (float*)d_out;                        // [512,64,256]

    float *p0 = nullptr, *p1 = nullptr, *pA = nullptr;
    cudaGetSymbolAddress((void**)&p0, g_buf0);
    cudaGetSymbolAddress((void**)&p1, g_buf1);
    cudaGetSymbolAddress((void**)&pA, g_A);

    // 1) dense normalized adjacency
    prep_A_kernel<<<1, 256>>>(edge_index, edge_weight, pA);

    // 2) pooling -> g_buf0 [512,64,256]
    pool_kernel<<<dim3(BATCH, 2), 128>>>(core_allocs, qubit_embs, dummy_emb, p0);

    // 3) three fused GCN layers
    gcn_layer_kernel<256, 512><<<dim3(512 / 64, BATCH), 256>>>(p0, W1, b1, pA, p1);
    gcn_layer_kernel<512, 512><<<dim3(512 / 64, BATCH), 256>>>(p1, W2, b2, pA, p0);
    gcn_layer_kernel<512, 256><<<dim3(256 / 64, BATCH), 256>>>(p0, W3, b3, pA, out);
}

// round 12
// speedup vs baseline: 1.1002x; 1.1002x over previous
#include <cuda_runtime.h>
#include <cuda_bf16.h>

#define N_CORES   64
#define N_QUBITS  1024
#define QEMB      256
#define N_EDGES   448
#define BATCH     512

// Scratch: ping-pong activation buffers, max width 512.
__device__ float g_buf0[BATCH * N_CORES * 512];
__device__ float g_buf1[BATCH * N_CORES * 512];
__device__ float g_A[N_CORES * N_CORES];

// ---------------------------------------------------------------------------
// Kernel 1: build dense normalized adjacency A[out*64 + src] (with self loops)
// ---------------------------------------------------------------------------
__global__ void prep_A_kernel(const int* __restrict__ eidx,
                              const float* __restrict__ ew,
                              float* __restrict__ A_out)
{
    __shared__ float sdeg[N_CORES];
    __shared__ float sdinv[N_CORES];
    __shared__ float sA[N_CORES * N_CORES];
    const int t = threadIdx.x;  // 256 threads

    if (t < N_CORES) sdeg[t] = 1.0f;  // self-loop weight
    for (int i = t; i < N_CORES * N_CORES; i += 256) sA[i] = 0.0f;
    __syncthreads();

    for (int e = t; e < N_EDGES; e += 256) {
        int c = eidx[N_EDGES + e];
        atomicAdd(&sdeg[c], ew[e]);
    }
    __syncthreads();

    if (t < N_CORES) sdinv[t] = 1.0f / sqrtf(sdeg[t]);  // deg >= 1 always
    __syncthreads();

    for (int e = t; e < N_EDGES; e += 256) {
        int r = eidx[e];
        int c = eidx[N_EDGES + e];
        atomicAdd(&sA[c * N_CORES + r], sdinv[r] * ew[e] * sdinv[c]);
    }
    if (t < N_CORES) {
        atomicAdd(&sA[t * N_CORES + t], sdinv[t] * sdinv[t]);  // self loop
    }
    __syncthreads();

    for (int i = t; i < N_CORES * N_CORES; i += 256) A_out[i] = sA[i];
}

// ---------------------------------------------------------------------------
// Kernel 2: pooling. grid = (BATCH, 2); block = 128 threads.
// Thread t owns dim d = half*128 + t for all 64 cores -> race-free smem max.
// ---------------------------------------------------------------------------
__global__ void pool_kernel(const int* __restrict__ core_allocs,
                            const float* __restrict__ qubit_embs,
                            const float* __restrict__ dummy_emb,
                            float* __restrict__ x0)
{
    __shared__ int   s_alloc[N_QUBITS];
    __shared__ float smax[N_CORES * 128];

    const int b    = blockIdx.x;
    const int half = blockIdx.y;
    const int t    = threadIdx.x;
    const int d    = half * 128 + t;

    const int* arow = core_allocs + b * N_QUBITS;
    for (int q = t; q < N_QUBITS; q += 128) s_alloc[q] = arow[q];

    const float dv = dummy_emb[d];
    #pragma unroll
    for (int c = 0; c < N_CORES; c++) smax[c * 128 + t] = dv;
    __syncthreads();

    #pragma unroll 4
    for (int q = 0; q < N_QUBITS; q++) {
        int c = s_alloc[q];
        float v = __ldg(&qubit_embs[q * QEMB + d]);
        float* p = &smax[c * 128 + t];
        *p = fmaxf(*p, v);
    }
    __syncthreads();

    float* xb = x0 + (size_t)b * N_CORES * QEMB;
    #pragma unroll
    for (int c = 0; c < N_CORES; c++) {
        xb[c * QEMB + d] = smax[c * 128 + t];
    }
}

// ---------------------------------------------------------------------------
// Kernel 3: fused GCN layer, 128x128 output tile (2 batches x 128 cols).
//   Phase 1: H[128x128] = X[128xDIN] @ W[:,n0:n0+128], 8x8 micro-tiles,
//            X staged k-major (transposed) in smem so A-operand vectorizes.
//   Phase 2: out = relu(blockdiag(A,A) @ H + b), via 4 strips of 32 cols
//            staged through the (reused) phase-1 smem buffer.
// grid = (DOUT/128, BATCH/2), block = 256.
// ---------------------------------------------------------------------------
template <int DIN, int DOUT>
__global__ __launch_bounds__(256, 2)
void gcn_layer_kernel(const float* __restrict__ x,
                      const float* __restrict__ W,
                      const float* __restrict__ bias,
                      const float* __restrict__ A,
                      float* __restrict__ out)
{
    // sAT: A transposed, k-major [64][68]  (sAT[k*68 + o] = A[o*64 + k])
    __shared__ float sAT[N_CORES * 68];
    // union buffer: phase1 = sXT[16][132] + sW[16][128]; phase2 = Hs[128][36]
    __shared__ float sbuf[128 * 36];
    float* sXT = sbuf;            // 16*132 = 2112
    float* sW  = sbuf + 2112;     // 16*128 = 2048  (total 4160 <= 4608)
    float* sHs = sbuf;            // 128*36 = 4608

    const int tid = threadIdx.x;
    const int tx  = tid & 15;
    const int ty  = tid >> 4;
    const int n0  = blockIdx.x * 128;
    const float* X = x + (size_t)blockIdx.y * 128 * DIN;  // 2 consecutive batches

    // Load A transposed into smem (once per block, tiny)
    for (int i = tid; i < N_CORES * N_CORES; i += 256) {
        int o = i >> 6, k = i & 63;
        sAT[k * 68 + o] = A[o * 64 + k];
    }

    float acc[8][8];
    #pragma unroll
    for (int i = 0; i < 8; i++)
        #pragma unroll
        for (int j = 0; j < 8; j++) acc[i][j] = 0.0f;

    // ---- Phase 1: K-chunks of 16 ----
    for (int k0 = 0; k0 < DIN; k0 += 16) {
        // X chunk [128 rows x 16 k] -> transposed into sXT[k][row] (stride 132)
        #pragma unroll
        for (int it = 0; it < 2; it++) {
            int idx = tid + it * 256;          // 0..511
            int r   = idx >> 2;                // 0..127
            int kq  = (idx & 3) * 4;           // 0,4,8,12
            float4 v = *(const float4*)(X + (size_t)r * DIN + k0 + kq);
            sXT[(kq + 0) * 132 + r] = v.x;
            sXT[(kq + 1) * 132 + r] = v.y;
            sXT[(kq + 2) * 132 + r] = v.z;
            sXT[(kq + 3) * 132 + r] = v.w;
        }
        // W chunk [16 k x 128 cols] -> sW (stride 128)
        #pragma unroll
        for (int it = 0; it < 2; it++) {
            int idx = tid + it * 256;
            int kk  = idx >> 5;                // 0..15
            int n4  = (idx & 31) * 4;          // 0..124
            *(float4*)&sW[kk * 128 + n4] =
                *(const float4*)(W + (size_t)(k0 + kk) * DOUT + n0 + n4);
        }
        __syncthreads();

        #pragma unroll 8
        for (int k = 0; k < 16; k++) {
            float4 a0 = *(float4*)&sXT[k * 132 + ty * 4];
            float4 a1 = *(float4*)&sXT[k * 132 + 64 + ty * 4];
            float4 w0 = *(float4*)&sW[k * 128 + tx * 4];
            float4 w1 = *(float4*)&sW[k * 128 + 64 + tx * 4];
            float av[8] = {a0.x, a0.y, a0.z, a0.w, a1.x, a1.y, a1.z, a1.w};
            float wv[8] = {w0.x, w0.y, w0.z, w0.w, w1.x, w1.y, w1.z, w1.w};
            #pragma unroll
            for (int i = 0; i < 8; i++)
                #pragma unroll
                for (int j = 0; j < 8; j++)
                    acc[i][j] += av[i] * wv[j];
        }
        __syncthreads();
    }

    // ---- Phase 2: 4 strips of 32 columns through sHs ----
    #pragma unroll
    for (int s = 0; s < 4; s++) {
        const int g = s >> 1;            // acc column half
        // owners write this strip's H columns
        if ((tx >> 3) == (s & 1)) {
            int sc = (tx & 7) * 4;       // col within strip
            #pragma unroll
            for (int i = 0; i < 8; i++) {
                int row = (i < 4) ? (ty * 4 + i) : (64 + ty * 4 + (i - 4));
                float4 v = make_float4(acc[i][g * 4 + 0], acc[i][g * 4 + 1],
                                       acc[i][g * 4 + 2], acc[i][g * 4 + 3]);
                *(float4*)&sHs[row * 36 + sc] = v;
            }
        }
        __syncthreads();

        float o[8][2];
        #pragma unroll
        for (int i = 0; i < 8; i++) { o[i][0] = 0.0f; o[i][1] = 0.0f; }

        #pragma unroll 8
        for (int k = 0; k < 64; k++) {
            float4 av = *(float4*)&sAT[k * 68 + ty * 4];
            float2 h0 = *(float2*)&sHs[k * 36 + tx * 2];
            float2 h1 = *(float2*)&sHs[(64 + k) * 36 + tx * 2];
            o[0][0] += av.x * h0.x;  o[0][1] += av.x * h0.y;
            o[1][0] += av.y * h0.x;  o[1][1] += av.y * h0.y;
            o[2][0] += av.z * h0.x;  o[2][1] += av.z * h0.y;
            o[3][0] += av.w * h0.x;  o[3][1] += av.w * h0.y;
            o[4][0] += av.x * h1.x;  o[4][1] += av.x * h1.y;
            o[5][0] += av.y * h1.x;  o[5][1] += av.y * h1.y;
            o[6][0] += av.z * h1.x;  o[6][1] += av.z * h1.y;
            o[7][0] += av.w * h1.x;  o[7][1] += av.w * h1.y;
        }

        float2 bv = *(const float2*)(bias + n0 + 32 * s + tx * 2);
        #pragma unroll
        for (int i = 0; i < 8; i++) {
            int batch = blockIdx.y * 2 + (i < 4 ? 0 : 1);
            int core  = ty * 4 + (i & 3);
            float2 r;
            r.x = fmaxf(o[i][0] + bv.x, 0.0f);
            r.y = fmaxf(o[i][1] + bv.y, 0.0f);
            *(float2*)(out + ((size_t)batch * 64 + core) * DOUT + n0 + 32 * s + tx * 2) = r;
        }
        if (s < 3) __syncthreads();
    }
}

// ---------------------------------------------------------------------------
// Launch
// ---------------------------------------------------------------------------
extern "C" void kernel_launch(void* const* d_in, const int* in_sizes, int n_in,
                              void* d_out, int out_size)
{
    const int*   core_allocs = (const int*)d_in[0];    // [512,1024]
    const float* qubit_embs  = (const float*)d_in[1];  // [1024,256]
    const float* dummy_emb   = (const float*)d_in[2];  // [256]
    const int*   edge_index  = (const int*)d_in[3];    // [2,448]
    const float* edge_weight = (const float*)d_in[4];  // [448]
    const float* W1 = (const float*)d_in[5];           // [256,512]
    const float* b1 = (const float*)d_in[6];           // [512]
    const float* W2 = (const float*)d_in[7];           // [512,512]
    const float* b2 = (const float*)d_in[8];           // [512]
    const float* W3 = (const float*)d_in[9];           // [512,256]
    const float* b3 = (const float*)d_in[10];          // [256]
    float* out = (float*)d_out;                        // [512,64,256]

    float *p0 = nullptr, *p1 = nullptr, *pA = nullptr;
    cudaGetSymbolAddress((void**)&p0, g_buf0);
    cudaGetSymbolAddress((void**)&p1, g_buf1);
    cudaGetSymbolAddress((void**)&pA, g_A);

    // 1) dense normalized adjacency
    prep_A_kernel<<<1, 256>>>(edge_index, edge_weight, pA);

    // 2) pooling -> g_buf0 [512,64,256]
    pool_kernel<<<dim3(BATCH, 2), 128>>>(core_allocs, qubit_embs, dummy_emb, p0);

    // 3) three fused GCN layers (128-row tiles = 2 batches per block)
    gcn_layer_kernel<256, 512><<<dim3(512 / 128, BATCH / 2), 256>>>(p0, W1, b1, pA, p1);
    gcn_layer_kernel<512, 512><<<dim3(512 / 128, BATCH / 2), 256>>>(p1, W2, b2, pA, p0);
    gcn_layer_kernel<512, 256><<<dim3(256 / 128, BATCH / 2), 256>>>(p0, W3, b3, pA, out);
}

// round 13
// speedup vs baseline: 1.1796x; 1.0722x over previous
#include <cuda_runtime.h>
#include <cuda_bf16.h>

#define N_CORES   64
#define N_QUBITS  1024
#define QEMB      256
#define N_EDGES   448
#define BATCH     512

// Scratch: ping-pong activation buffers, max width 512.
__device__ float g_buf0[BATCH * N_CORES * 512];
__device__ float g_buf1[BATCH * N_CORES * 512];
__device__ float g_A[N_CORES * N_CORES];

// ---------------- packed f32x2 helpers (Blackwell FFMA2 path) ----------------
__device__ __forceinline__ unsigned long long ffma2(unsigned long long a,
                                                    unsigned long long b,
                                                    unsigned long long c)
{
    unsigned long long d;
    asm("fma.rn.f32x2 %0, %1, %2, %3;" : "=l"(d) : "l"(a), "l"(b), "l"(c));
    return d;
}
__device__ __forceinline__ unsigned long long pack2(float x, float y)
{
    unsigned long long r;
    asm("mov.b64 %0, {%1, %2};" : "=l"(r) : "f"(x), "f"(y));
    return r;
}
__device__ __forceinline__ float2 unpack2(unsigned long long v)
{
    float2 r;
    asm("mov.b64 {%0, %1}, %2;" : "=f"(r.x), "=f"(r.y) : "l"(v));
    return r;
}

// ---------------------------------------------------------------------------
// Kernel 1: dense normalized adjacency A[out*64 + src] (with self loops)
// ---------------------------------------------------------------------------
__global__ void prep_A_kernel(const int* __restrict__ eidx,
                              const float* __restrict__ ew,
                              float* __restrict__ A_out)
{
    __shared__ float sdeg[N_CORES];
    __shared__ float sdinv[N_CORES];
    __shared__ float sA[N_CORES * N_CORES];
    const int t = threadIdx.x;  // 256 threads

    if (t < N_CORES) sdeg[t] = 1.0f;
    for (int i = t; i < N_CORES * N_CORES; i += 256) sA[i] = 0.0f;
    __syncthreads();

    for (int e = t; e < N_EDGES; e += 256) {
        int c = eidx[N_EDGES + e];
        atomicAdd(&sdeg[c], ew[e]);
    }
    __syncthreads();

    if (t < N_CORES) sdinv[t] = 1.0f / sqrtf(sdeg[t]);
    __syncthreads();

    for (int e = t; e < N_EDGES; e += 256) {
        int r = eidx[e];
        int c = eidx[N_EDGES + e];
        atomicAdd(&sA[c * N_CORES + r], sdinv[r] * ew[e] * sdinv[c]);
    }
    if (t < N_CORES) atomicAdd(&sA[t * N_CORES + t], sdinv[t] * sdinv[t]);
    __syncthreads();

    for (int i = t; i < N_CORES * N_CORES; i += 256) A_out[i] = sA[i];
}

// ---------------------------------------------------------------------------
// Kernel 2: pooling. grid = (BATCH, 2); block = 128 threads.
// ---------------------------------------------------------------------------
__global__ void pool_kernel(const int* __restrict__ core_allocs,
                            const float* __restrict__ qubit_embs,
                            const float* __restrict__ dummy_emb,
                            float* __restrict__ x0)
{
    __shared__ int   s_alloc[N_QUBITS];
    __shared__ float smax[N_CORES * 128];

    const int b    = blockIdx.x;
    const int half = blockIdx.y;
    const int t    = threadIdx.x;
    const int d    = half * 128 + t;

    const int* arow = core_allocs + b * N_QUBITS;
    for (int q = t; q < N_QUBITS; q += 128) s_alloc[q] = arow[q];

    const float dv = dummy_emb[d];
    #pragma unroll
    for (int c = 0; c < N_CORES; c++) smax[c * 128 + t] = dv;
    __syncthreads();

    #pragma unroll 4
    for (int q = 0; q < N_QUBITS; q++) {
        int c = s_alloc[q];
        float v = __ldg(&qubit_embs[q * QEMB + d]);
        float* p = &smax[c * 128 + t];
        *p = fmaxf(*p, v);
    }
    __syncthreads();

    float* xb = x0 + (size_t)b * N_CORES * QEMB;
    #pragma unroll
    for (int c = 0; c < N_CORES; c++) {
        xb[c * QEMB + d] = smax[c * 128 + t];
    }
}

// ---------------------------------------------------------------------------
// Kernel 3: fused GCN layer, 128x128 output tile (2 batches x 128 cols).
//   Phase 1: H = X @ W tile, 8x8 micro-tiles via packed FFMA2 (f32x2).
//   Phase 2: out = relu(blockdiag(A,A) @ H + b) via 4 strips of 32 cols.
// grid = (DOUT/128, BATCH/2), block = 256.
// ---------------------------------------------------------------------------
template <int DIN, int DOUT>
__global__ __launch_bounds__(256, 2)
void gcn_layer_kernel(const float* __restrict__ x,
                      const float* __restrict__ W,
                      const float* __restrict__ bias,
                      const float* __restrict__ A,
                      float* __restrict__ out)
{
    // union buffer:
    //   phase1: sXT[32][132] (4224) + sW[32][128] (4096) = 8320
    //   phase2: sHs[128][36] (4608) + sAT[64][68]  (4352) = 8960
    __shared__ float sbuf[8960];
    float* sXT = sbuf;            // k-major transposed X chunk
    float* sW  = sbuf + 4224;
    float* sHs = sbuf;            // phase-2 H strip
    float* sAT = sbuf + 4608;     // A transposed, k-major

    const int tid = threadIdx.x;
    const int tx  = tid & 15;
    const int ty  = tid >> 4;
    const int n0  = blockIdx.x * 128;
    const float* X = x + (size_t)blockIdx.y * 128 * DIN;  // 2 consecutive batches

    // packed accumulators: acc2[i][jp] covers cols pairs
    //   jp0: (tx*4+0, +1)   jp1: (tx*4+2, +3)
    //   jp2: (64+tx*4+0,+1) jp3: (64+tx*4+2,+3)
    unsigned long long acc2[8][4];
    #pragma unroll
    for (int i = 0; i < 8; i++)
        #pragma unroll
        for (int j = 0; j < 4; j++) acc2[i][j] = 0ull;

    // ---- Phase 1: K-chunks of 32 ----
    for (int k0 = 0; k0 < DIN; k0 += 32) {
        // X chunk [128 rows x 32 k] -> transposed sXT[k][row] (stride 132)
        #pragma unroll
        for (int it = 0; it < 4; it++) {
            int idx = tid + it * 256;          // 0..1023 float4 slots
            int r   = idx >> 3;                // 0..127
            int kq  = (idx & 7) * 4;           // 0..28
            float4 v = *(const float4*)(X + (size_t)r * DIN + k0 + kq);
            sXT[(kq + 0) * 132 + r] = v.x;
            sXT[(kq + 1) * 132 + r] = v.y;
            sXT[(kq + 2) * 132 + r] = v.z;
            sXT[(kq + 3) * 132 + r] = v.w;
        }
        // W chunk [32 k x 128 cols] -> sW (stride 128)
        #pragma unroll
        for (int it = 0; it < 4; it++) {
            int idx = tid + it * 256;
            int kk  = idx >> 5;                // 0..31
            int n4  = (idx & 31) * 4;          // 0..124
            *(float4*)&sW[kk * 128 + n4] =
                *(const float4*)(W + (size_t)(k0 + kk) * DOUT + n0 + n4);
        }
        __syncthreads();

        #pragma unroll 8
        for (int k = 0; k < 32; k++) {
            float4 a0 = *(float4*)&sXT[k * 132 + ty * 4];
            float4 a1 = *(float4*)&sXT[k * 132 + 64 + ty * 4];
            ulonglong2 w0 = *(ulonglong2*)&sW[k * 128 + tx * 4];
            ulonglong2 w1 = *(ulonglong2*)&sW[k * 128 + 64 + tx * 4];
            float av[8] = {a0.x, a0.y, a0.z, a0.w, a1.x, a1.y, a1.z, a1.w};
            #pragma unroll
            for (int i = 0; i < 8; i++) {
                unsigned long long ad = pack2(av[i], av[i]);
                acc2[i][0] = ffma2(w0.x, ad, acc2[i][0]);
                acc2[i][1] = ffma2(w0.y, ad, acc2[i][1]);
                acc2[i][2] = ffma2(w1.x, ad, acc2[i][2]);
                acc2[i][3] = ffma2(w1.y, ad, acc2[i][3]);
            }
        }
        __syncthreads();
    }

    // ---- load A (transposed, k-major) into union buffer ----
    for (int i = tid; i < N_CORES * N_CORES; i += 256) {
        int c = i >> 6, k = i & 63;
        sAT[k * 68 + c] = A[i];   // A[c*64 + k]
    }

    // ---- Phase 2: 4 strips of 32 columns ----
    #pragma unroll
    for (int s = 0; s < 4; s++) {
        const int g = s >> 1;            // acc column half
        if ((tx >> 3) == (s & 1)) {
            int sc = (tx & 7) * 4;       // col within strip
            #pragma unroll
            for (int i = 0; i < 8; i++) {
                int row = (i < 4) ? (ty * 4 + i) : (64 + ty * 4 + (i - 4));
                ulonglong2 v;
                v.x = acc2[i][g * 2 + 0];
                v.y = acc2[i][g * 2 + 1];
                *(ulonglong2*)&sHs[row * 36 + sc] = v;
            }
        }
        __syncthreads();

        unsigned long long o2[8];
        #pragma unroll
        for (int i = 0; i < 8; i++) o2[i] = 0ull;

        #pragma unroll 8
        for (int k = 0; k < 64; k++) {
            float4 av = *(float4*)&sAT[k * 68 + ty * 4];
            unsigned long long h0 = *(unsigned long long*)&sHs[k * 36 + tx * 2];
            unsigned long long h1 = *(unsigned long long*)&sHs[(64 + k) * 36 + tx * 2];
            unsigned long long dx = pack2(av.x, av.x);
            unsigned long long dy = pack2(av.y, av.y);
            unsigned long long dz = pack2(av.z, av.z);
            unsigned long long dw = pack2(av.w, av.w);
            o2[0] = ffma2(h0, dx, o2[0]);
            o2[1] = ffma2(h0, dy, o2[1]);
            o2[2] = ffma2(h0, dz, o2[2]);
            o2[3] = ffma2(h0, dw, o2[3]);
            o2[4] = ffma2(h1, dx, o2[4]);
            o2[5] = ffma2(h1, dy, o2[5]);
            o2[6] = ffma2(h1, dz, o2[6]);
            o2[7] = ffma2(h1, dw, o2[7]);
        }

        float2 bv = *(const float2*)(bias + n0 + 32 * s + tx * 2);
        #pragma unroll
        for (int i = 0; i < 8; i++) {
            int batch = blockIdx.y * 2 + (i < 4 ? 0 : 1);
            int core  = ty * 4 + (i & 3);
            float2 ov = unpack2(o2[i]);
            float2 r;
            r.x = fmaxf(ov.x + bv.x, 0.0f);
            r.y = fmaxf(ov.y + bv.y, 0.0f);
            *(float2*)(out + ((size_t)batch * 64 + core) * DOUT + n0 + 32 * s + tx * 2) = r;
        }
        if (s < 3) __syncthreads();
    }
}

// ---------------------------------------------------------------------------
// Launch
// ---------------------------------------------------------------------------
extern "C" void kernel_launch(void* const* d_in, const int* in_sizes, int n_in,
                              void* d_out, int out_size)
{
    const int*   core_allocs = (const int*)d_in[0];    // [512,1024]
    const float* qubit_embs  = (const float*)d_in[1];  // [1024,256]
    const float* dummy_emb   = (const float*)d_in[2];  // [256]
    const int*   edge_index  = (const int*)d_in[3];    // [2,448]
    const float* edge_weight = (const float*)d_in[4];  // [448]
    const float* W1 = (const float*)d_in[5];           // [256,512]
    const float* b1 = (const float*)d_in[6];           // [512]
    const float* W2 = (const float*)d_in[7];           // [512,512]
    const float* b2 = (const float*)d_in[8];           // [512]
    const float* W3 = (const float*)d_in[9];           // [512,256]
    const float* b3 = (const float*)d_in[10];          // [256]
    float* out = (float*)d_out;                        // [512,64,256]

    float *p0 = nullptr, *p1 = nullptr, *pA = nullptr;
    cudaGetSymbolAddress((void**)&p0, g_buf0);
    cudaGetSymbolAddress((void**)&p1, g_buf1);
    cudaGetSymbolAddress((void**)&pA, g_A);

    // 1) dense normalized adjacency
    prep_A_kernel<<<1, 256>>>(edge_index, edge_weight, pA);

    // 2) pooling -> g_buf0 [512,64,256]
    pool_kernel<<<dim3(BATCH, 2), 128>>>(core_allocs, qubit_embs, dummy_emb, p0);

    // 3) three fused GCN layers (128-row tiles = 2 batches per block)
    gcn_layer_kernel<256, 512><<<dim3(512 / 128, BATCH / 2), 256>>>(p0, W1, b1, pA, p1);
    gcn_layer_kernel<512, 512><<<dim3(512 / 128, BATCH / 2), 256>>>(p1, W2, b2, pA, p0);
    gcn_layer_kernel<512, 256><<<dim3(256 / 128, BATCH / 2), 256>>>(p0, W3, b3, pA, out);
}

// round 14
// speedup vs baseline: 1.1898x; 1.0087x over previous
#include <cuda_runtime.h>
#include <cuda_bf16.h>

#define N_CORES   64
#define N_QUBITS  1024
#define QEMB      256
#define N_EDGES   448
#define BATCH     512

// Scratch: ping-pong activation buffers, max width 512.
__device__ float g_buf0[BATCH * N_CORES * 512];
__device__ float g_buf1[BATCH * N_CORES * 512];
__device__ float g_A[N_CORES * N_CORES];

// ---------------- packed f32x2 helpers (Blackwell FFMA2 path) ----------------
__device__ __forceinline__ unsigned long long ffma2(unsigned long long a,
                                                    unsigned long long b,
                                                    unsigned long long c)
{
    unsigned long long d;
    asm("fma.rn.f32x2 %0, %1, %2, %3;" : "=l"(d) : "l"(a), "l"(b), "l"(c));
    return d;
}
__device__ __forceinline__ unsigned long long pack2(float x, float y)
{
    unsigned long long r;
    asm("mov.b64 %0, {%1, %2};" : "=l"(r) : "f"(x), "f"(y));
    return r;
}
__device__ __forceinline__ float2 unpack2(unsigned long long v)
{
    float2 r;
    asm("mov.b64 {%0, %1}, %2;" : "=f"(r.x), "=f"(r.y) : "l"(v));
    return r;
}

// ---------------------------------------------------------------------------
// Kernel 1: dense normalized adjacency A[out*64 + src] (with self loops)
// ---------------------------------------------------------------------------
__global__ void prep_A_kernel(const int* __restrict__ eidx,
                              const float* __restrict__ ew,
                              float* __restrict__ A_out)
{
    __shared__ float sdeg[N_CORES];
    __shared__ float sdinv[N_CORES];
    __shared__ float sA[N_CORES * N_CORES];
    const int t = threadIdx.x;  // 256 threads

    if (t < N_CORES) sdeg[t] = 1.0f;
    for (int i = t; i < N_CORES * N_CORES; i += 256) sA[i] = 0.0f;
    __syncthreads();

    for (int e = t; e < N_EDGES; e += 256) {
        int c = eidx[N_EDGES + e];
        atomicAdd(&sdeg[c], ew[e]);
    }
    __syncthreads();

    if (t < N_CORES) sdinv[t] = 1.0f / sqrtf(sdeg[t]);
    __syncthreads();

    for (int e = t; e < N_EDGES; e += 256) {
        int r = eidx[e];
        int c = eidx[N_EDGES + e];
        atomicAdd(&sA[c * N_CORES + r], sdinv[r] * ew[e] * sdinv[c]);
    }
    if (t < N_CORES) atomicAdd(&sA[t * N_CORES + t], sdinv[t] * sdinv[t]);
    __syncthreads();

    for (int i = t; i < N_CORES * N_CORES; i += 256) A_out[i] = sA[i];
}

// ---------------------------------------------------------------------------
// Kernel 2: pooling. grid = (BATCH, 2); block = 128 threads.
// ---------------------------------------------------------------------------
__global__ void pool_kernel(const int* __restrict__ core_allocs,
                            const float* __restrict__ qubit_embs,
                            const float* __restrict__ dummy_emb,
                            float* __restrict__ x0)
{
    __shared__ int   s_alloc[N_QUBITS];
    __shared__ float smax[N_CORES * 128];

    const int b    = blockIdx.x;
    const int half = blockIdx.y;
    const int t    = threadIdx.x;
    const int d    = half * 128 + t;

    const int* arow = core_allocs + b * N_QUBITS;
    for (int q = t; q < N_QUBITS; q += 128) s_alloc[q] = arow[q];

    const float dv = dummy_emb[d];
    #pragma unroll
    for (int c = 0; c < N_CORES; c++) smax[c * 128 + t] = dv;
    __syncthreads();

    #pragma unroll 4
    for (int q = 0; q < N_QUBITS; q++) {
        int c = s_alloc[q];
        float v = __ldg(&qubit_embs[q * QEMB + d]);
        float* p = &smax[c * 128 + t];
        *p = fmaxf(*p, v);
    }
    __syncthreads();

    float* xb = x0 + (size_t)b * N_CORES * QEMB;
    #pragma unroll
    for (int c = 0; c < N_CORES; c++) {
        xb[c * QEMB + d] = smax[c * 128 + t];
    }
}

// ---------------------------------------------------------------------------
// Kernel 3: fused GCN layer, 128x128 output tile (2 batches x 128 cols).
//   Phase 1: H = X @ W tile, 8x8 micro-tiles via packed FFMA2 (f32x2).
//   Phase 2: out = relu(blockdiag(A,A) @ H + b) via 4 strips of 32 cols.
// grid = (DOUT/128, BATCH/2), block = 256.
// ---------------------------------------------------------------------------
template <int DIN, int DOUT>
__global__ __launch_bounds__(256, 2)
void gcn_layer_kernel(const float* __restrict__ x,
                      const float* __restrict__ W,
                      const float* __restrict__ bias,
                      const float* __restrict__ A,
                      float* __restrict__ out)
{
    // union buffer:
    //   phase1: sXT[32][132] (4224) + sW[32][128] (4096) = 8320
    //   phase2: sHs[128][36] (4608) + sAT[64][68]  (4352) = 8960
    __shared__ float sbuf[8960];
    float* sXT = sbuf;            // k-major transposed X chunk
    float* sW  = sbuf + 4224;
    float* sHs = sbuf;            // phase-2 H strip
    float* sAT = sbuf + 4608;     // A transposed, k-major

    const int tid = threadIdx.x;
    const int tx  = tid & 15;
    const int ty  = tid >> 4;
    const int n0  = blockIdx.x * 128;
    const float* X = x + (size_t)blockIdx.y * 128 * DIN;  // 2 consecutive batches

    // packed accumulators: acc2[i][jp] covers cols pairs
    //   jp0: (tx*4+0, +1)   jp1: (tx*4+2, +3)
    //   jp2: (64+tx*4+0,+1) jp3: (64+tx*4+2,+3)
    unsigned long long acc2[8][4];
    #pragma unroll
    for (int i = 0; i < 8; i++)
        #pragma unroll
        for (int j = 0; j < 4; j++) acc2[i][j] = 0ull;

    // ---- Phase 1: K-chunks of 32 ----
    for (int k0 = 0; k0 < DIN; k0 += 32) {
        // X chunk [128 rows x 32 k] -> transposed sXT[k][row] (stride 132)
        #pragma unroll
        for (int it = 0; it < 4; it++) {
            int idx = tid + it * 256;          // 0..1023 float4 slots
            int r   = idx >> 3;                // 0..127
            int kq  = (idx & 7) * 4;           // 0..28
            float4 v = *(const float4*)(X + (size_t)r * DIN + k0 + kq);
            sXT[(kq + 0) * 132 + r] = v.x;
            sXT[(kq + 1) * 132 + r] = v.y;
            sXT[(kq + 2) * 132 + r] = v.z;
            sXT[(kq + 3) * 132 + r] = v.w;
        }
        // W chunk [32 k x 128 cols] -> sW (stride 128)
        #pragma unroll
        for (int it = 0; it < 4; it++) {
            int idx = tid + it * 256;
            int kk  = idx >> 5;                // 0..31
            int n4  = (idx & 31) * 4;          // 0..124
            *(float4*)&sW[kk * 128 + n4] =
                *(const float4*)(W + (size_t)(k0 + kk) * DOUT + n0 + n4);
        }
        __syncthreads();

        #pragma unroll 8
        for (int k = 0; k < 32; k++) {
            float4 a0 = *(float4*)&sXT[k * 132 + ty * 4];
            float4 a1 = *(float4*)&sXT[k * 132 + 64 + ty * 4];
            ulonglong2 w0 = *(ulonglong2*)&sW[k * 128 + tx * 4];
            ulonglong2 w1 = *(ulonglong2*)&sW[k * 128 + 64 + tx * 4];
            float av[8] = {a0.x, a0.y, a0.z, a0.w, a1.x, a1.y, a1.z, a1.w};
            #pragma unroll
            for (int i = 0; i < 8; i++) {
                unsigned long long ad = pack2(av[i], av[i]);
                acc2[i][0] = ffma2(w0.x, ad, acc2[i][0]);
                acc2[i][1] = ffma2(w0.y, ad, acc2[i][1]);
                acc2[i][2] = ffma2(w1.x, ad, acc2[i][2]);
                acc2[i][3] = ffma2(w1.y, ad, acc2[i][3]);
            }
        }
        __syncthreads();
    }

    // ---- load A (transposed, k-major) into union buffer ----
    for (int i = tid; i < N_CORES * N_CORES; i += 256) {
        int c = i >> 6, k = i & 63;
        sAT[k * 68 + c] = A[i];   // A[c*64 + k]
    }

    // ---- Phase 2: 4 strips of 32 columns ----
    #pragma unroll
    for (int s = 0; s < 4; s++) {
        const int g = s >> 1;            // acc column half
        if ((tx >> 3) == (s & 1)) {
            int sc = (tx & 7) * 4;       // col within strip
            #pragma unroll
            for (int i = 0; i < 8; i++) {
                int row = (i < 4) ? (ty * 4 + i) : (64 + ty * 4 + (i - 4));
                ulonglong2 v;
                v.x = acc2[i][g * 2 + 0];
                v.y = acc2[i][g * 2 + 1];
                *(ulonglong2*)&sHs[row * 36 + sc] = v;
            }
        }
        __syncthreads();

        unsigned long long o2[8];
        #pragma unroll
        for (int i = 0; i < 8; i++) o2[i] = 0ull;

        #pragma unroll 8
        for (int k = 0; k < 64; k++) {
            float4 av = *(float4*)&sAT[k * 68 + ty * 4];
            unsigned long long h0 = *(unsigned long long*)&sHs[k * 36 + tx * 2];
            unsigned long long h1 = *(unsigned long long*)&sHs[(64 + k) * 36 + tx * 2];
            unsigned long long dx = pack2(av.x, av.x);
            unsigned long long dy = pack2(av.y, av.y);
            unsigned long long dz = pack2(av.z, av.z);
            unsigned long long dw = pack2(av.w, av.w);
            o2[0] = ffma2(h0, dx, o2[0]);
            o2[1] = ffma2(h0, dy, o2[1]);
            o2[2] = ffma2(h0, dz, o2[2]);
            o2[3] = ffma2(h0, dw, o2[3]);
            o2[4] = ffma2(h1, dx, o2[4]);
            o2[5] = ffma2(h1, dy, o2[5]);
            o2[6] = ffma2(h1, dz, o2[6]);
            o2[7] = ffma2(h1, dw, o2[7]);
        }

        float2 bv = *(const float2*)(bias + n0 + 32 * s + tx * 2);
        #pragma unroll
        for (int i = 0; i < 8; i++) {
            int batch = blockIdx.y * 2 + (i < 4 ? 0 : 1);
            int core  = ty * 4 + (i & 3);
            float2 ov = unpack2(o2[i]);
            float2 r;
            r.x = fmaxf(ov.x + bv.x, 0.0f);
            r.y = fmaxf(ov.y + bv.y, 0.0f);
            *(float2*)(out + ((size_t)batch * 64 + core) * DOUT + n0 + 32 * s + tx * 2) = r;
        }
        if (s < 3) __syncthreads();
    }
}

// ---------------------------------------------------------------------------
// Launch
// ---------------------------------------------------------------------------
extern "C" void kernel_launch(void* const* d_in, const int* in_sizes, int n_in,
                              void* d_out, int out_size)
{
    const int*   core_allocs = (const int*)d_in[0];    // [512,1024]
    const float* qubit_embs  = (const float*)d_in[1];  // [1024,256]
    const float* dummy_emb   = (const float*)d_in[2];  // [256]
    const int*   edge_index  = (const int*)d_in[3];    // [2,448]
    const float* edge_weight = (const float*)d_in[4];  // [448]
    const float* W1 = (const float*)d_in[5];           // [256,512]
    const float* b1 = (const float*)d_in[6];           // [512]
    const float* W2 = (const float*)d_in[7];           // [512,512]
    const float* b2 = (const float*)d_in[8];           // [512]
    const float* W3 = (const float*)d_in[9];           // [512,256]
    const float* b3 = (const float*)d_in[10];          // [256]
    float* out = (float*)d_out;                        // [512,64,256]

    float *p0 = nullptr, *p1 = nullptr, *pA = nullptr;
    cudaGetSymbolAddress((void**)&p0, g_buf0);
    cudaGetSymbolAddress((void**)&p1, g_buf1);
    cudaGetSymbolAddress((void**)&pA, g_A);

    // 1) dense normalized adjacency
    prep_A_kernel<<<1, 256>>>(edge_index, edge_weight, pA);

    // 2) pooling -> g_buf0 [512,64,256]
    pool_kernel<<<dim3(BATCH, 2), 128>>>(core_allocs, qubit_embs, dummy_emb, p0);

    // 3) three fused GCN layers (128-row tiles = 2 batches per block)
    gcn_layer_kernel<256, 512><<<dim3(512 / 128, BATCH / 2), 256>>>(p0, W1, b1, pA, p1);
    gcn_layer_kernel<512, 512><<<dim3(512 / 128, BATCH / 2), 256>>>(p1, W2, b2, pA, p0);
    gcn_layer_kernel<512, 256><<<dim3(256 / 128, BATCH / 2), 256>>>(p0, W3, b3, pA, out);
}